// round 1
// baseline (speedup 1.0000x reference)
#include <cuda_runtime.h>

// CategorySpecificLinear: y[b,t,:] = x[b,t,:] @ W[cat_ids[b]] + bias[cat_ids[b]]
// Shapes: x[64,512,1024] f32, cat_ids[64] i32, W[32,1024,1024] f32, bias[32,1024] f32
// Output: y[64,512,1024] f32
//
// Round 1: fp32 SMEM-tiled register-blocked SGEMM baseline.
// BM=128 (tokens) x BN=128 (outputs) x BK=16, 256 threads, 8x8 per thread.
// grid = (O/128, T/128, B) = (8, 4, 64) = 2048 CTAs.

#define BM 128
#define BN 128
#define BK 16
#define TM 8
#define TN 8

__global__ __launch_bounds__(256, 2)
void cslin_sgemm_kernel(const float* __restrict__ x,
                        const int*   __restrict__ cat_ids,
                        const float* __restrict__ W,
                        const float* __restrict__ bias,
                        float*       __restrict__ y)
{
    constexpr int Tdim = 512;
    constexpr int Idim = 1024;
    constexpr int Odim = 1024;

    const int n0 = blockIdx.x * BN;   // output-col tile
    const int m0 = blockIdx.y * BM;   // token-row tile
    const int bb = blockIdx.z;        // batch element

    const int cat = cat_ids[bb];
    const float* xb = x + (size_t)bb  * Tdim * Idim;
    const float* Wc = W + (size_t)cat * Idim * Odim;
    const float* bc = bias + (size_t)cat * Odim;
    float*       yb = y + (size_t)bb  * Tdim * Odim;

    __shared__ float As[BK][BM];   // x tile, transposed: As[k][m]
    __shared__ float Bs[BK][BN];   // W tile: Bs[k][n]

    const int tid = threadIdx.x;
    const int tn  = (tid & 15) * TN;   // 16 threads across N
    const int tm  = (tid >> 4) * TM;   // 16 threads across M

    float acc[TM][TN] = {};
    float ra[TM], rb[TN];

    for (int k0 = 0; k0 < Idim; k0 += BK) {
        // ---- load x tile (BM x BK) into As transposed ----
        // 128*16 floats = 512 float4 loads, 2 per thread
        #pragma unroll
        for (int j = 0; j < 2; j++) {
            int f    = tid + 256 * j;
            int row  = f >> 2;           // token row within tile, 0..127
            int col4 = (f & 3) << 2;     // k offset: 0,4,8,12
            float4 v = *(const float4*)(xb + (size_t)(m0 + row) * Idim + k0 + col4);
            As[col4 + 0][row] = v.x;
            As[col4 + 1][row] = v.y;
            As[col4 + 2][row] = v.z;
            As[col4 + 3][row] = v.w;
        }
        // ---- load W tile (BK x BN) into Bs ----
        #pragma unroll
        for (int j = 0; j < 2; j++) {
            int f    = tid + 256 * j;
            int row  = f >> 5;           // k row, 0..15
            int col4 = (f & 31) << 2;    // n offset, 0..124
            *(float4*)(&Bs[row][col4]) =
                *(const float4*)(Wc + (size_t)(k0 + row) * Odim + n0 + col4);
        }
        __syncthreads();

        // ---- 8x8 register-blocked FMA ----
        #pragma unroll
        for (int k = 0; k < BK; k++) {
            #pragma unroll
            for (int i = 0; i < TM; i++) ra[i] = As[k][tm + i];
            #pragma unroll
            for (int j = 0; j < TN; j++) rb[j] = Bs[k][tn + j];
            #pragma unroll
            for (int i = 0; i < TM; i++)
                #pragma unroll
                for (int j = 0; j < TN; j++)
                    acc[i][j] = fmaf(ra[i], rb[j], acc[i][j]);
        }
        __syncthreads();
    }

    // ---- epilogue: add bias, store ----
    #pragma unroll
    for (int i = 0; i < TM; i++) {
        float* out_row = yb + (size_t)(m0 + tm + i) * Odim + n0 + tn;
        #pragma unroll
        for (int j = 0; j < TN; j += 4) {
            float4 v;
            v.x = acc[i][j + 0] + bc[n0 + tn + j + 0];
            v.y = acc[i][j + 1] + bc[n0 + tn + j + 1];
            v.z = acc[i][j + 2] + bc[n0 + tn + j + 2];
            v.w = acc[i][j + 3] + bc[n0 + tn + j + 3];
            *(float4*)(out_row + j) = v;
        }
    }
}

extern "C" void kernel_launch(void* const* d_in, const int* in_sizes, int n_in,
                              void* d_out, int out_size)
{
    const float* x       = (const float*)d_in[0];  // [64,512,1024]
    const int*   cat_ids = (const int*)  d_in[1];  // [64]
    const float* W       = (const float*)d_in[2];  // [32,1024,1024]
    const float* bias    = (const float*)d_in[3];  // [32,1024]
    float*       y       = (float*)d_out;          // [64,512,1024]

    dim3 grid(1024 / BN, 512 / BM, 64);  // (8, 4, 64)
    cslin_sgemm_kernel<<<grid, 256>>>(x, cat_ids, W, bias, y);
}

// round 3
// speedup vs baseline: 3.0981x; 3.0981x over previous
#include <cuda_runtime.h>
#include <cstdint>

// CategorySpecificLinear via mma.sync.m16n8k8 TF32 (base sm_103 feature set —
// tcgen05 is unavailable: this bench's PTX targets sm_103, not sm_103a).
//
// y[b,t,:] = x[b,t,:] @ W[cat_ids[b]] + bias[cat_ids[b]]
// x[64,512,1024] f32, W[32,1024,1024] f32, bias[32,1024] f32 -> y[64,512,1024] f32
//
// CTA tile 128(M) x 128(N) x K=1024, chunks of BK=32, double-buffered SMEM.
// 8 warps, warp tile 64x32 = 4x4 m16n8k8 fragments, fp32 accum in registers.
// Inputs rounded to TF32 with cvt.rna at the STS stage (rel_err ~ 4e-4).

#define STAGE_A 16384                 // 128 x 32 f32, swizzled 128B rows
#define STAGE_B 16896                 // 32 x 132 f32 (pad 4)
#define B_OFF   (2 * STAGE_A)
#define SMEM_DYN (2 * STAGE_A + 2 * STAGE_B)   // 66560 B

static __device__ __forceinline__ uint32_t f2tf(float f){
    uint32_t r; asm("cvt.rna.tf32.f32 %0, %1;" : "=r"(r) : "f"(f)); return r;
}

static __device__ __forceinline__ void mma_tf32(float d[4],
                                                uint32_t a0, uint32_t a1,
                                                uint32_t a2, uint32_t a3,
                                                uint32_t b0, uint32_t b1){
    asm volatile(
        "mma.sync.aligned.m16n8k8.row.col.f32.tf32.tf32.f32 "
        "{%0,%1,%2,%3}, {%4,%5,%6,%7}, {%8,%9}, {%0,%1,%2,%3};"
        : "+f"(d[0]), "+f"(d[1]), "+f"(d[2]), "+f"(d[3])
        : "r"(a0), "r"(a1), "r"(a2), "r"(a3), "r"(b0), "r"(b1));
}

__global__ __launch_bounds__(256, 2)
void cslin_mma_kernel(const float* __restrict__ x,
                      const int*   __restrict__ cat_ids,
                      const float* __restrict__ W,
                      const float* __restrict__ bias,
                      float*       __restrict__ y)
{
    constexpr int IDIM = 1024, ODIM = 1024, TDIM = 512;
    extern __shared__ char dsm[];

    const int tid  = threadIdx.x;
    const int wid  = tid >> 5;
    const int lane = tid & 31;
    const int la3  = lane & 3;       // threadID_in_group
    const int lg   = lane >> 2;      // groupID

    const int n0 = blockIdx.x * 128;
    const int m0 = blockIdx.y * 128;
    const int bb = blockIdx.z;
    const int cat = __ldg(cat_ids + bb);

    const float* xb = x + (size_t)bb  * TDIM * IDIM;
    const float* Wc = W + (size_t)cat * IDIM * ODIM;
    const float* bc = bias + (size_t)cat * ODIM;
    float*       yb = y + (size_t)bb  * TDIM * ODIM;

    // ---- loader geometry (per thread, constant across chunks) ----
    // A chunk: 128m x 32k, 4 float4/thread: m = (tid>>3)+32i, k4 = (tid&7)*4
    const float* aG = xb + (size_t)(m0 + (tid >> 3)) * IDIM + ((tid & 7) << 2);
    // STS A: 128B rows, swizzled column. (m&7) is constant per thread.
    const uint32_t aScol = (uint32_t)(((tid & 7) << 4) ^ ((((tid >> 3) & 7)) << 4));
    const uint32_t aSrow = (uint32_t)((tid >> 3) * 128);
    // B chunk: 32k x 128n, 4 float4/thread: k = (tid>>5)+8i, n4 = (tid&31)*4
    const float* bG = Wc + (size_t)(tid >> 5) * ODIM + n0 + ((tid & 31) << 2);
    const uint32_t bSoff = (uint32_t)(((tid >> 5) * 132 + ((tid & 31) << 2)) * 4);

    // ---- warp tile position ----
    const int wm = (wid & 1) * 64;          // M offset: 0 / 64
    const int wn = (wid >> 1) * 32;         // N offset: 0/32/64/96

    // a-frag row byte offsets (swizzle xor constant = (lg&7)<<4 since wm+i*16 ≡ 0 mod 8)
    const uint32_t swzA = (uint32_t)((lg & 7) << 4);
    uint32_t rA[4];
    #pragma unroll
    for (int i = 0; i < 4; i++) rA[i] = (uint32_t)((wm + i * 16 + lg) * 128);
    // b-frag n byte offsets
    uint32_t bN[4];
    #pragma unroll
    for (int j = 0; j < 4; j++) bN[j] = (uint32_t)((wn + j * 8 + lg) * 4);

    float acc[4][4][4];
    #pragma unroll
    for (int i = 0; i < 4; i++)
        #pragma unroll
        for (int j = 0; j < 4; j++)
            #pragma unroll
            for (int q = 0; q < 4; q++) acc[i][j][q] = 0.f;

    float4 av[4], bv[4];

    // ---- prologue: chunk 0 ----
    #pragma unroll
    for (int i = 0; i < 4; i++){
        av[i] = *(const float4*)(aG + (size_t)i * 32 * IDIM);
        bv[i] = *(const float4*)(bG + (size_t)i * 8 * ODIM);
    }
    {
        char* stA = dsm;            char* stB = dsm + B_OFF;
        #pragma unroll
        for (int i = 0; i < 4; i++){
            *(uint4*)(stA + aSrow + (uint32_t)i * 4096 + aScol) =
                make_uint4(f2tf(av[i].x), f2tf(av[i].y), f2tf(av[i].z), f2tf(av[i].w));
            *(uint4*)(stB + bSoff + (uint32_t)i * 4224) =
                make_uint4(f2tf(bv[i].x), f2tf(bv[i].y), f2tf(bv[i].z), f2tf(bv[i].w));
        }
    }
    __syncthreads();

    // ---- main loop over 32 K-chunks ----
    for (int c = 0; c < 32; c++){
        const int s = c & 1;
        if (c < 31){
            const int kc = (c + 1) * 32;
            #pragma unroll
            for (int i = 0; i < 4; i++){
                av[i] = *(const float4*)(aG + (size_t)i * 32 * IDIM + kc);
                bv[i] = *(const float4*)(bG + (size_t)(kc + i * 8) * ODIM);
            }
        }

        // compute on stage s
        {
            const char* stA = dsm + s * STAGE_A;
            const char* stB = dsm + B_OFF + s * STAGE_B;
            #pragma unroll
            for (int ks = 0; ks < 4; ks++){
                uint32_t b0[4], b1[4];
                const uint32_t krow = (uint32_t)((ks * 8 + la3) * 528);  // 132 f32 * 4B
                #pragma unroll
                for (int j = 0; j < 4; j++){
                    const char* p = stB + krow + bN[j];
                    b0[j] = *(const uint32_t*)p;
                    b1[j] = *(const uint32_t*)(p + 2112);                 // +4 k-rows
                }
                const uint32_t c0 = (uint32_t)((ks * 32 + la3 * 4)) ^ swzA;
                const uint32_t c1 = (uint32_t)((ks * 32 + la3 * 4 + 16)) ^ swzA;
                #pragma unroll
                for (int i = 0; i < 4; i++){
                    const char* pa = stA + rA[i];
                    const uint32_t a0 = *(const uint32_t*)(pa + c0);
                    const uint32_t a1 = *(const uint32_t*)(pa + 1024 + c0);
                    const uint32_t a2 = *(const uint32_t*)(pa + c1);
                    const uint32_t a3 = *(const uint32_t*)(pa + 1024 + c1);
                    #pragma unroll
                    for (int j = 0; j < 4; j++)
                        mma_tf32(acc[i][j], a0, a1, a2, a3, b0[j], b1[j]);
                }
            }
        }

        if (c < 31){
            char* stA = dsm + (s ^ 1) * STAGE_A;
            char* stB = dsm + B_OFF + (s ^ 1) * STAGE_B;
            #pragma unroll
            for (int i = 0; i < 4; i++){
                *(uint4*)(stA + aSrow + (uint32_t)i * 4096 + aScol) =
                    make_uint4(f2tf(av[i].x), f2tf(av[i].y), f2tf(av[i].z), f2tf(av[i].w));
                *(uint4*)(stB + bSoff + (uint32_t)i * 4224) =
                    make_uint4(f2tf(bv[i].x), f2tf(bv[i].y), f2tf(bv[i].z), f2tf(bv[i].w));
            }
            __syncthreads();
        }
    }

    // ---- epilogue: acc + bias -> y ----
    float bias0[4], bias1[4];
    #pragma unroll
    for (int j = 0; j < 4; j++){
        const int gn = n0 + wn + j * 8 + la3 * 2;
        bias0[j] = __ldg(bc + gn);
        bias1[j] = __ldg(bc + gn + 1);
    }
    #pragma unroll
    for (int i = 0; i < 4; i++){
        const int gm = m0 + wm + i * 16 + lg;
        #pragma unroll
        for (int j = 0; j < 4; j++){
            const int gn = n0 + wn + j * 8 + la3 * 2;
            float2 v0 = make_float2(acc[i][j][0] + bias0[j], acc[i][j][1] + bias1[j]);
            float2 v1 = make_float2(acc[i][j][2] + bias0[j], acc[i][j][3] + bias1[j]);
            *(float2*)(yb + (size_t)gm * ODIM + gn)       = v0;
            *(float2*)(yb + (size_t)(gm + 8) * ODIM + gn) = v1;
        }
    }
}

extern "C" void kernel_launch(void* const* d_in, const int* in_sizes, int n_in,
                              void* d_out, int out_size)
{
    const float* x       = (const float*)d_in[0];
    const int*   cat_ids = (const int*)  d_in[1];
    const float* W       = (const float*)d_in[2];
    const float* bias    = (const float*)d_in[3];
    float*       y       = (float*)d_out;

    cudaFuncSetAttribute(cslin_mma_kernel,
                         cudaFuncAttributeMaxDynamicSharedMemorySize, SMEM_DYN);
    dim3 grid(1024 / 128, 512 / 128, 64);   // (8, 4, 64)
    cslin_mma_kernel<<<grid, 256, SMEM_DYN>>>(x, cat_ids, W, bias, y);
}

// round 4
// speedup vs baseline: 3.5880x; 1.1581x over previous
#include <cuda_runtime.h>
#include <cstdint>

// CategorySpecificLinear via mma.sync.m16n8k8 TF32 (base sm_103 — tcgen05 is
// rejected by this bench's ptxas target).
//
// y[b,t,:] = x[b,t,:] @ W[cat_ids[b]] + bias[cat_ids[b]]
// x[64,512,1024] f32, W[32,1024,1024] f32, bias[32,1024] f32 -> y[64,512,1024] f32
//
// Round 4: CTA tile 256(M) x 128(N) x BK=32, 8 warps as 4Mx2N, warp tile 64x64
// (4x8 m16n8k8 frags). 1.0 LDS.32 per MMA (was 1.5), B rows padded to 136 f32
// for conflict-free b-frag loads. Double-buffered SMEM, fp32->tf32 via cvt.rna.

#define STAGE_A 32768                 // 256 x 32 f32, swizzled 128B rows
#define STAGE_B 17408                 // 32 x 136 f32 (pad 8)
#define B_OFF   (2 * STAGE_A)
#define SMEM_DYN (2 * STAGE_A + 2 * STAGE_B)   // 100352 B

static __device__ __forceinline__ uint32_t f2tf(float f){
    uint32_t r; asm("cvt.rna.tf32.f32 %0, %1;" : "=r"(r) : "f"(f)); return r;
}

static __device__ __forceinline__ void mma_tf32(float d[4],
                                                uint32_t a0, uint32_t a1,
                                                uint32_t a2, uint32_t a3,
                                                uint32_t b0, uint32_t b1){
    asm volatile(
        "mma.sync.aligned.m16n8k8.row.col.f32.tf32.tf32.f32 "
        "{%0,%1,%2,%3}, {%4,%5,%6,%7}, {%8,%9}, {%0,%1,%2,%3};"
        : "+f"(d[0]), "+f"(d[1]), "+f"(d[2]), "+f"(d[3])
        : "r"(a0), "r"(a1), "r"(a2), "r"(a3), "r"(b0), "r"(b1));
}

__global__ __launch_bounds__(256, 1)
void cslin_mma2_kernel(const float* __restrict__ x,
                       const int*   __restrict__ cat_ids,
                       const float* __restrict__ W,
                       const float* __restrict__ bias,
                       float*       __restrict__ y)
{
    constexpr int IDIM = 1024, ODIM = 1024, TDIM = 512;
    extern __shared__ char dsm[];

    const int tid  = threadIdx.x;
    const int wid  = tid >> 5;
    const int lane = tid & 31;
    const int la3  = lane & 3;       // threadID_in_group
    const int lg   = lane >> 2;      // groupID (0..7)

    const int n0 = blockIdx.x * 128;
    const int m0 = blockIdx.y * 256;
    const int bb = blockIdx.z;
    const int cat = __ldg(cat_ids + bb);

    const float* xb = x + (size_t)bb  * TDIM * IDIM;
    const float* Wc = W + (size_t)cat * IDIM * ODIM;
    const float* bc = bias + (size_t)cat * ODIM;
    float*       yb = y + (size_t)bb  * TDIM * ODIM;

    // ---- loader geometry ----
    // A chunk 256m x 32k: 8 float4/thread: m = (tid>>3) + 32i, k4 = (tid&7)*4
    const float* aG = xb + (size_t)(m0 + (tid >> 3)) * IDIM + ((tid & 7) << 2);
    const uint32_t aScol = (uint32_t)((((tid & 7) << 4)) ^ ((((tid >> 3) & 7)) << 4));
    const uint32_t aSrow = (uint32_t)((tid >> 3) * 128);      // +i*4096
    // B chunk 32k x 128n: 4 float4/thread: k = tid>>3, n = (tid&7)*4 + 32i
    const float* bG = Wc + (size_t)(tid >> 3) * ODIM + n0 + ((tid & 7) << 2);
    const uint32_t bSoff = (uint32_t)(((tid >> 3) * 136 + ((tid & 7) << 2)) * 4); // +i*128

    // ---- warp tile: 64x64 at (wm, wn) ----
    const int wm = (wid & 3) * 64;          // 0/64/128/192
    const int wn = (wid >> 2) * 64;         // 0/64

    const uint32_t swzA = (uint32_t)(lg << 4);
    uint32_t rA[4];
    #pragma unroll
    for (int i = 0; i < 4; i++) rA[i] = (uint32_t)((wm + i * 16 + lg) * 128);
    uint32_t bN[8];
    #pragma unroll
    for (int j = 0; j < 8; j++) bN[j] = (uint32_t)((wn + j * 8 + lg) * 4);

    float acc[4][8][4];
    #pragma unroll
    for (int i = 0; i < 4; i++)
        #pragma unroll
        for (int j = 0; j < 8; j++)
            #pragma unroll
            for (int q = 0; q < 4; q++) acc[i][j][q] = 0.f;

    float4 av[8], bv[4];

    // ---- prologue: chunk 0 ----
    #pragma unroll
    for (int i = 0; i < 8; i++) av[i] = *(const float4*)(aG + (size_t)i * 32 * IDIM);
    #pragma unroll
    for (int i = 0; i < 4; i++) bv[i] = *(const float4*)(bG + 32 * i);
    {
        char* stA = dsm;            char* stB = dsm + B_OFF;
        #pragma unroll
        for (int i = 0; i < 8; i++)
            *(uint4*)(stA + aSrow + (uint32_t)i * 4096 + aScol) =
                make_uint4(f2tf(av[i].x), f2tf(av[i].y), f2tf(av[i].z), f2tf(av[i].w));
        #pragma unroll
        for (int i = 0; i < 4; i++)
            *(uint4*)(stB + bSoff + (uint32_t)i * 128) =
                make_uint4(f2tf(bv[i].x), f2tf(bv[i].y), f2tf(bv[i].z), f2tf(bv[i].w));
    }
    __syncthreads();

    // ---- main loop: 32 K-chunks ----
    for (int c = 0; c < 32; c++){
        const int s = c & 1;
        if (c < 31){
            const int kc = (c + 1) * 32;
            #pragma unroll
            for (int i = 0; i < 8; i++)
                av[i] = *(const float4*)(aG + (size_t)i * 32 * IDIM + kc);
            #pragma unroll
            for (int i = 0; i < 4; i++)
                bv[i] = *(const float4*)(bG + (size_t)kc * ODIM + 32 * i);
        }

        // compute on stage s
        {
            const char* stA = dsm + s * STAGE_A;
            const char* stB = dsm + B_OFF + s * STAGE_B;
            #pragma unroll
            for (int ks = 0; ks < 4; ks++){
                uint32_t b0[8], b1[8];
                const uint32_t krow = (uint32_t)((ks * 8 + la3) * 544);  // 136 f32 rows
                #pragma unroll
                for (int j = 0; j < 8; j++){
                    const char* p = stB + krow + bN[j];
                    b0[j] = *(const uint32_t*)p;
                    b1[j] = *(const uint32_t*)(p + 2176);                // +4 k-rows
                }
                const uint32_t c0 = ((uint32_t)(ks * 32 + la3 * 4)) ^ swzA;
                const uint32_t c1 = c0 ^ 16u;
                #pragma unroll
                for (int i = 0; i < 4; i++){
                    const char* pa = stA + rA[i];
                    const uint32_t a0 = *(const uint32_t*)(pa + c0);
                    const uint32_t a1 = *(const uint32_t*)(pa + 1024 + c0);
                    const uint32_t a2 = *(const uint32_t*)(pa + c1);
                    const uint32_t a3 = *(const uint32_t*)(pa + 1024 + c1);
                    #pragma unroll
                    for (int j = 0; j < 8; j++)
                        mma_tf32(acc[i][j], a0, a1, a2, a3, b0[j], b1[j]);
                }
            }
        }

        if (c < 31){
            char* stA = dsm + (s ^ 1) * STAGE_A;
            char* stB = dsm + B_OFF + (s ^ 1) * STAGE_B;
            #pragma unroll
            for (int i = 0; i < 8; i++)
                *(uint4*)(stA + aSrow + (uint32_t)i * 4096 + aScol) =
                    make_uint4(f2tf(av[i].x), f2tf(av[i].y), f2tf(av[i].z), f2tf(av[i].w));
            #pragma unroll
            for (int i = 0; i < 4; i++)
                *(uint4*)(stB + bSoff + (uint32_t)i * 128) =
                    make_uint4(f2tf(bv[i].x), f2tf(bv[i].y), f2tf(bv[i].z), f2tf(bv[i].w));
            __syncthreads();
        }
    }

    // ---- epilogue: acc + bias -> y ----
    float bias0[8], bias1[8];
    #pragma unroll
    for (int j = 0; j < 8; j++){
        const int gn = n0 + wn + j * 8 + la3 * 2;
        bias0[j] = __ldg(bc + gn);
        bias1[j] = __ldg(bc + gn + 1);
    }
    #pragma unroll
    for (int i = 0; i < 4; i++){
        const int gm = m0 + wm + i * 16 + lg;
        #pragma unroll
        for (int j = 0; j < 8; j++){
            const int gn = n0 + wn + j * 8 + la3 * 2;
            float2 v0 = make_float2(acc[i][j][0] + bias0[j], acc[i][j][1] + bias1[j]);
            float2 v1 = make_float2(acc[i][j][2] + bias0[j], acc[i][j][3] + bias1[j]);
            *(float2*)(yb + (size_t)gm * ODIM + gn)       = v0;
            *(float2*)(yb + (size_t)(gm + 8) * ODIM + gn) = v1;
        }
    }
}

extern "C" void kernel_launch(void* const* d_in, const int* in_sizes, int n_in,
                              void* d_out, int out_size)
{
    const float* x       = (const float*)d_in[0];
    const int*   cat_ids = (const int*)  d_in[1];
    const float* W       = (const float*)d_in[2];
    const float* bias    = (const float*)d_in[3];
    float*       y       = (float*)d_out;

    cudaFuncSetAttribute(cslin_mma2_kernel,
                         cudaFuncAttributeMaxDynamicSharedMemorySize, SMEM_DYN);
    dim3 grid(1024 / 128, 512 / 256, 64);   // (8, 2, 64)
    cslin_mma2_kernel<<<grid, 256, SMEM_DYN>>>(x, cat_ids, W, bias, y);
}